// round 12
// baseline (speedup 1.0000x reference)
#include <cuda_runtime.h>
#include <cuda_bf16.h>
#include <math.h>
#include <stdint.h>

// Problem constants
#define BATCH 256
#define TLEN  512
#define DIM   1024
#define VOCAB 32000

// Persistent tiling: 128 CTAs (1/SM); CTA bid -> (kc = bid>>4 of 8, nc = bid&15 of 16)
//   GEMM tile: 256 batch rows x 64 cols x 128 K.  LN rows: b = 2*bid + (tid>>7).
#define NK 8
#define NN 16
#define KT 128
#define NT 64
#define NCTA 128
#define CK 32                 // K-chunk per cp.async stage (4 per step)

// Logits tiling
#define VT 128
#define BT 32

// SMEM layout (dynamic):
//  sW: [2 splits][128 k][72 bf16]  stride 144B -> 2 x 18432 = 36864 B
//  sA: [4 chunks][2 splits][256 m][40 bf16] stride 80B -> per split 20480 B
#define SM_W    0
#define W_SPL   18432u
#define WSTRIDE 144u
#define SM_A    36864
#define ASTRIDE 80u
#define ASPL    20480u        // per-split (256 rows x 80B)
#define ACH     40960u        // per-chunk (2 splits)
#define SMEM_BYTES (36864 + 4 * 40960)   // 200704

// ---------------------------------------------------------------------------
// Device scratch (static — no cudaMalloc allowed)
// ---------------------------------------------------------------------------
__device__ float         g_P[NK][BATCH][DIM];     // partial sums
__device__ __nv_bfloat16 g_Uhi[BATCH][DIM], g_Ulo[BATCH][DIM];  // u row-major, split
__device__ __nv_bfloat16 g_Hhi[BATCH][DIM], g_Hlo[BATCH][DIM];  // hidden row-major, split
__device__ unsigned g_bar_arrive = 0;
__device__ unsigned g_bar_gen    = 0;

// ---------------------------------------------------------------------------
// PTX helpers
// ---------------------------------------------------------------------------
__device__ __forceinline__ uint32_t smem_u32(const void* p) {
    uint32_t a;
    asm("{ .reg .u64 t; cvta.to.shared.u64 t, %1; cvt.u32.u64 %0, t; }" : "=r"(a) : "l"(p));
    return a;
}
__device__ __forceinline__ void cp_async16(uint32_t dst, const void* src) {
    asm volatile("cp.async.cg.shared.global [%0], [%1], 16;" :: "r"(dst), "l"(src) : "memory");
}
#define CP_COMMIT() asm volatile("cp.async.commit_group;" ::: "memory")
#define CP_WAIT(n)  asm volatile("cp.async.wait_group %0;" :: "n"(n) : "memory")

// non-trans x4 (A fragment, row-major [m][k])
__device__ __forceinline__ void ldm_x4(uint32_t* r, uint32_t addr) {
    asm volatile("ldmatrix.sync.aligned.m8n8.x4.shared.b16 {%0,%1,%2,%3}, [%4];"
                 : "=r"(r[0]), "=r"(r[1]), "=r"(r[2]), "=r"(r[3]) : "r"(addr));
}
// trans x2 (B fragment from W [k][n])
__device__ __forceinline__ void ldm_x2_t(uint32_t* r, uint32_t addr) {
    asm volatile("ldmatrix.sync.aligned.m8n8.x2.trans.shared.b16 {%0,%1}, [%2];"
                 : "=r"(r[0]), "=r"(r[1]) : "r"(addr));
}
__device__ __forceinline__ void mma_bf16(float* c, const uint32_t* a, const uint32_t* b) {
    asm volatile(
        "mma.sync.aligned.m16n8k16.row.col.f32.bf16.bf16.f32 "
        "{%0,%1,%2,%3}, {%4,%5,%6,%7}, {%8,%9}, {%0,%1,%2,%3};"
        : "+f"(c[0]), "+f"(c[1]), "+f"(c[2]), "+f"(c[3])
        : "r"(a[0]), "r"(a[1]), "r"(a[2]), "r"(a[3]), "r"(b[0]), "r"(b[1]));
}
__device__ __forceinline__ uint32_t pack_bf16x2(float a, float b) {
    const __nv_bfloat16 ba = __float2bfloat16(a);
    const __nv_bfloat16 bb = __float2bfloat16(b);
    return (uint32_t)__bfloat16_as_ushort(ba) | ((uint32_t)__bfloat16_as_ushort(bb) << 16);
}
// split 8 fp32 channels -> bf16 hi/lo, store as 2x16B (.cg)
__device__ __forceinline__ void split_store8(__nv_bfloat16* hp, __nv_bfloat16* lp,
                                             const float* v)
{
    uint32_t h[4], l[4];
    #pragma unroll
    for (int q = 0; q < 4; ++q) {
        const float a = v[2*q], b = v[2*q+1];
        h[q] = pack_bf16x2(a, b);
        const float la = a - __bfloat162float(__float2bfloat16(a));
        const float lb = b - __bfloat162float(__float2bfloat16(b));
        l[q] = pack_bf16x2(la, lb);
    }
    __stcg((uint4*)hp, make_uint4(h[0], h[1], h[2], h[3]));
    __stcg((uint4*)lp, make_uint4(l[0], l[1], l[2], l[3]));
}

// ---------------------------------------------------------------------------
// Grid-wide barrier (sense-reversing; 128 CTAs, 1/SM, all co-resident)
// ---------------------------------------------------------------------------
__device__ __forceinline__ void grid_barrier()
{
    __threadfence();
    __syncthreads();
    if (threadIdx.x == 0) {
        unsigned gen = *(volatile unsigned*)&g_bar_gen;
        if (atomicAdd(&g_bar_arrive, 1u) == NCTA - 1u) {
            atomicExch(&g_bar_arrive, 0u);
            __threadfence();
            atomicAdd(&g_bar_gen, 1u);
        } else {
            while (*(volatile unsigned*)&g_bar_gen == gen) { }
        }
        __threadfence();
    }
    __syncthreads();
}

// ---------------------------------------------------------------------------
// W tile load: fp32 Wdt -> smem bf16 hi/lo, [k][n] stride 144B
// ---------------------------------------------------------------------------
__device__ __forceinline__ void load_w(char* smp, const float* __restrict__ Wdt,
                                       int half, int k0, int n0, int tid)
{
    #pragma unroll
    for (int t = 0; t < 32; ++t) {
        const int i = tid + t * 256;      // 0..8191
        const int k = i >> 6;
        const int n = i & 63;
        const float v = Wdt[(size_t)(half * DIM + k0 + k) * DIM + n0 + n];
        const __nv_bfloat16 hi = __float2bfloat16(v);
        const __nv_bfloat16 lo = __float2bfloat16(v - __bfloat162float(hi));
        *(__nv_bfloat16*)(smp + SM_W + (uint32_t)k * WSTRIDE + (uint32_t)n * 2u) = hi;
        *(__nv_bfloat16*)(smp + SM_W + W_SPL + (uint32_t)k * WSTRIDE + (uint32_t)n * 2u) = lo;
    }
}

// cp.async one 32-k chunk of A (hi+lo): 256 rows x 64B x 2 splits = 2048 x 16B
__device__ __forceinline__ void issue_chunk(uint32_t sa_base,
    const __nv_bfloat16* __restrict__ srchi, const __nv_bfloat16* __restrict__ srclo,
    int kglob, int tid)
{
    #pragma unroll
    for (int t = 0; t < 8; ++t) {
        const int i  = tid + t * 256;     // 0..2047
        const int sp = i >> 10;           // 0..1 (1024 transfers per split)
        const int r  = (i >> 2) & 255;    // row 0..255
        const int c  = i & 3;             // 16B column; 4 cols x 16B = 64B = 32 bf16
        const __nv_bfloat16* src = (sp ? srclo : srchi) + (size_t)r * DIM + kglob + c * 8;
        const uint32_t dst = sa_base + (uint32_t)sp * ASPL + (uint32_t)r * ASTRIDE + (uint32_t)c * 16u;
        cp_async16(dst, src);
    }
    CP_COMMIT();
}

// ---------------------------------------------------------------------------
// Compute one 32-k chunk: 2 ksteps x (2 m x 8 n x 3 split products)
// A row-major [m][k] stride 80B (non-trans); W [k][n] stride 144B (trans).
// B fragments in 2 groups of 4 n-tiles (register pressure).
// ---------------------------------------------------------------------------
__device__ __forceinline__ void compute_chunk(uint32_t abase, uint32_t wbase, int c,
                                              float acc[2][8][4], int lane, int wid)
{
    #pragma unroll
    for (int ks = 0; ks < 2; ++ks) {
        // A fragments (within-chunk k 0..31) — loaded once, reused by both groups
        const uint32_t arow = (uint32_t)(wid * 32 + (lane & 15));
        const uint32_t acol = (uint32_t)(ks * 32 + (lane >> 4) * 16);
        uint32_t ah[2][4], al[2][4];
        #pragma unroll
        for (int mt = 0; mt < 2; ++mt) {
            const uint32_t off = (arow + (uint32_t)mt * 16u) * ASTRIDE + acol;
            ldm_x4(ah[mt], abase + off);
            ldm_x4(al[mt], abase + ASPL + off);
        }
        const uint32_t krow_b = (uint32_t)(c * CK + ks * 16 + (lane & 15));
        #pragma unroll
        for (int g = 0; g < 2; ++g) {
            uint32_t bh[4][2], bl[4][2];
            #pragma unroll
            for (int j = 0; j < 4; ++j) {
                const uint32_t nb = (uint32_t)(g * 4 + j) * 16u;
                ldm_x2_t(bh[j], wbase + 0u    + krow_b * WSTRIDE + nb);
                ldm_x2_t(bl[j], wbase + W_SPL + krow_b * WSTRIDE + nb);
            }
            #pragma unroll
            for (int mt = 0; mt < 2; ++mt)
                #pragma unroll
                for (int j = 0; j < 4; ++j) {
                    float* a = acc[mt][g * 4 + j];
                    mma_bf16(a, ah[mt], bh[j]);
                    mma_bf16(a, ah[mt], bl[j]);
                    mma_bf16(a, al[mt], bh[j]);
                }
        }
    }
}

// ---------------------------------------------------------------------------
// One full step GEMM: P[kc][256 b][n0..n0+63] over K [k0, k0+128)
// 4 chunks of K=32, all issued up front; incremental waits.
// ---------------------------------------------------------------------------
__device__ __forceinline__ void gemm_step_mma(char* smp, uint32_t base,
    const __nv_bfloat16* __restrict__ srchi, const __nv_bfloat16* __restrict__ srclo,
    int k0, int n0, int kc, int tid)
{
    const int lane = tid & 31, wid = tid >> 5;
    float acc[2][8][4];
    #pragma unroll
    for (int mt = 0; mt < 2; ++mt)
        #pragma unroll
        for (int nt = 0; nt < 8; ++nt)
            #pragma unroll
            for (int q = 0; q < 4; ++q) acc[mt][nt][q] = 0.f;

    const uint32_t wb = base + SM_W;
    #pragma unroll
    for (int c = 0; c < 4; ++c)
        issue_chunk(base + SM_A + (uint32_t)c * ACH, srchi, srclo, k0 + c * CK, tid);

    CP_WAIT(3); __syncthreads();
    compute_chunk(base + SM_A + 0u * ACH, wb, 0, acc, lane, wid);
    CP_WAIT(2); __syncthreads();
    compute_chunk(base + SM_A + 1u * ACH, wb, 1, acc, lane, wid);
    CP_WAIT(1); __syncthreads();
    compute_chunk(base + SM_A + 2u * ACH, wb, 2, acc, lane, wid);
    CP_WAIT(0); __syncthreads();
    compute_chunk(base + SM_A + 3u * ACH, wb, 3, acc, lane, wid);

    // store accumulators -> g_P[kc] (warp wid owns rows wid*32..+31)
    const int r4 = lane >> 2, c2 = (lane & 3) * 2;
    #pragma unroll
    for (int mt = 0; mt < 2; ++mt)
        #pragma unroll
        for (int nt = 0; nt < 8; ++nt) {
            const int r0 = wid * 32 + mt * 16 + r4;
            const int cc = n0 + nt * 8 + c2;
            __stcg((float2*)&g_P[kc][r0][cc],     make_float2(acc[mt][nt][0], acc[mt][nt][1]));
            __stcg((float2*)&g_P[kc][r0 + 8][cc], make_float2(acc[mt][nt][2], acc[mt][nt][3]));
        }
}

// ---------------------------------------------------------------------------
// Persistent scan kernel: init + c precompute + 512 x (HMMA GEMM, LN)
// ---------------------------------------------------------------------------
__global__ __launch_bounds__(256) void rnn_persistent(
    const float* __restrict__ hidden, const int* __restrict__ tok,
    const float* __restrict__ emb,    const float* __restrict__ Wdt,
    const float* __restrict__ bdt,    const float* __restrict__ gamma,
    const float* __restrict__ beta,   float* __restrict__ zout)
{
    extern __shared__ char smp[];
    const uint32_t base = smem_u32(smp);
    __shared__ float red[2][2][4];   // [row][stat][warp-of-row]

    const int tid = threadIdx.x;
    const int bid = blockIdx.x;
    const int nc = bid & 15, kc = bid >> 4;
    const int n0 = nc * NT,  k0 = kc * KT;

    // LN role: 2 rows per CTA
    const int row_sel = tid >> 7;
    const int b  = bid * 2 + row_sel;
    const int lt = tid & 127;
    const int d0 = lt * 8;
    const int wr = (tid >> 5) & 3;

    // ---- init: row-major bf16 splits of hidden and u0 (8 channels/thread) ----
    float ur[8], gm[8], bt[8];
    {
        const int tk0 = tok[(size_t)b * TLEN];
        float hv[8];
        const float4 h0 = *(const float4*)&hidden[(size_t)b * DIM + d0];
        const float4 h1 = *(const float4*)&hidden[(size_t)b * DIM + d0 + 4];
        hv[0]=h0.x; hv[1]=h0.y; hv[2]=h0.z; hv[3]=h0.w;
        hv[4]=h1.x; hv[5]=h1.y; hv[6]=h1.z; hv[7]=h1.w;
        const float4 u0 = *(const float4*)&emb[(size_t)tk0 * DIM + d0];
        const float4 u1 = *(const float4*)&emb[(size_t)tk0 * DIM + d0 + 4];
        ur[0]=u0.x; ur[1]=u0.y; ur[2]=u0.z; ur[3]=u0.w;
        ur[4]=u1.x; ur[5]=u1.y; ur[6]=u1.z; ur[7]=u1.w;
        split_store8(&g_Hhi[b][d0], &g_Hlo[b][d0], hv);
        split_store8(&g_Uhi[b][d0], &g_Ulo[b][d0], ur);
        const float4 g0 = *(const float4*)&gamma[d0];
        const float4 g1 = *(const float4*)&gamma[d0 + 4];
        gm[0]=g0.x; gm[1]=g0.y; gm[2]=g0.z; gm[3]=g0.w;
        gm[4]=g1.x; gm[5]=g1.y; gm[6]=g1.z; gm[7]=g1.w;
        const float4 b0 = *(const float4*)&beta[d0];
        const float4 b1 = *(const float4*)&beta[d0 + 4];
        bt[0]=b0.x; bt[1]=b0.y; bt[2]=b0.z; bt[3]=b0.w;
        bt[4]=b1.x; bt[5]=b1.y; bt[6]=b1.z; bt[7]=b1.w;
    }

    // ---- c = hidden @ W_bot + b_dt ----
    load_w(smp, Wdt, 1, k0, n0, tid);
    grid_barrier();                     // H/U splits visible everywhere
    gemm_step_mma(smp, base, &g_Hhi[0][0], &g_Hlo[0][0], k0, n0, kc, tid);
    grid_barrier();                     // g_P complete

    float cre[8];
    {
        #pragma unroll
        for (int j = 0; j < 8; ++j) cre[j] = 0.f;
        #pragma unroll
        for (int j = 0; j < NK; ++j) {
            const float4 p0 = __ldcg((const float4*)&g_P[j][b][d0]);
            const float4 p1 = __ldcg((const float4*)&g_P[j][b][d0 + 4]);
            cre[0] += p0.x; cre[1] += p0.y; cre[2] += p0.z; cre[3] += p0.w;
            cre[4] += p1.x; cre[5] += p1.y; cre[6] += p1.z; cre[7] += p1.w;
        }
        const float4 bd0 = *(const float4*)&bdt[d0];
        const float4 bd1 = *(const float4*)&bdt[d0 + 4];
        cre[0]+=bd0.x; cre[1]+=bd0.y; cre[2]+=bd0.z; cre[3]+=bd0.w;
        cre[4]+=bd1.x; cre[5]+=bd1.y; cre[6]+=bd1.z; cre[7]+=bd1.w;
    }

    __syncthreads();
    load_w(smp, Wdt, 0, k0, n0, tid);   // W_top, persistent for the scan
    grid_barrier();                     // P consumed before step 0 overwrites

    // ---- scan ----
    for (int t = 0; t < TLEN; ++t) {
        // prefetch next-token embedding
        float ev[8];
        if (t < TLEN - 1) {
            const int tkn = tok[(size_t)b * TLEN + t + 1];
            const float4 e0 = *(const float4*)&emb[(size_t)tkn * DIM + d0];
            const float4 e1 = *(const float4*)&emb[(size_t)tkn * DIM + d0 + 4];
            ev[0]=e0.x; ev[1]=e0.y; ev[2]=e0.z; ev[3]=e0.w;
            ev[4]=e1.x; ev[5]=e1.y; ev[6]=e1.z; ev[7]=e1.w;
        }

        gemm_step_mma(smp, base, &g_Uhi[0][0], &g_Ulo[0][0], k0, n0, kc, tid);
        grid_barrier();

        // LN: y = C + U + sum_j P[j]
        float y[8];
        #pragma unroll
        for (int j = 0; j < 8; ++j) y[j] = cre[j] + ur[j];
        #pragma unroll
        for (int j = 0; j < NK; ++j) {
            const float4 p0 = __ldcg((const float4*)&g_P[j][b][d0]);
            const float4 p1 = __ldcg((const float4*)&g_P[j][b][d0 + 4]);
            y[0] += p0.x; y[1] += p0.y; y[2] += p0.z; y[3] += p0.w;
            y[4] += p1.x; y[5] += p1.y; y[6] += p1.z; y[7] += p1.w;
        }

        float s1 = 0.f, s2 = 0.f;
        #pragma unroll
        for (int j = 0; j < 8; ++j) { s1 += y[j]; s2 += y[j] * y[j]; }
        #pragma unroll
        for (int o = 16; o; o >>= 1) {
            s1 += __shfl_xor_sync(0xffffffffu, s1, o);
            s2 += __shfl_xor_sync(0xffffffffu, s2, o);
        }
        if ((tid & 31) == 0) { red[row_sel][0][wr] = s1; red[row_sel][1][wr] = s2; }
        __syncthreads();
        float t1 = 0.f, t2 = 0.f;
        #pragma unroll
        for (int j = 0; j < 4; ++j) {
            t1 += red[row_sel][0][j];
            t2 += red[row_sel][1][j];
        }
        __syncthreads();

        const float mean = t1 * (1.f / DIM);
        const float var  = t2 * (1.f / DIM) - mean * mean;
        const float rstd = rsqrtf(var + 1e-5f);

        float sv[8];
        #pragma unroll
        for (int j = 0; j < 8; ++j)
            sv[j] = (y[j] - mean) * rstd * gm[j] + bt[j];

        if (t < TLEN - 1) {
            float un[8];
            #pragma unroll
            for (int j = 0; j < 8; ++j) { un[j] = sv[j] + ev[j]; ur[j] = un[j]; }
            split_store8(&g_Uhi[b][d0], &g_Ulo[b][d0], un);
        } else {
            *(float4*)&zout[(size_t)b * DIM + d0] =
                make_float4(sv[0], sv[1], sv[2], sv[3]);
            *(float4*)&zout[(size_t)b * DIM + d0 + 4] =
                make_float4(sv[4], sv[5], sv[6], sv[7]);
        }
        grid_barrier();
    }
}

// ---------------------------------------------------------------------------
// Packed f32x2 helpers (logits kernel)
// ---------------------------------------------------------------------------
__device__ __forceinline__ unsigned long long pack2(float lo, float hi)
{
    unsigned long long r;
    asm("mov.b64 %0, {%1, %2};" : "=l"(r) : "f"(lo), "f"(hi));
    return r;
}
__device__ __forceinline__ float2 unpack2(unsigned long long v)
{
    float2 r;
    asm("mov.b64 {%0, %1}, %2;" : "=f"(r.x), "=f"(r.y) : "l"(v));
    return r;
}
__device__ __forceinline__ void ffma2(unsigned long long& acc,
                                      unsigned long long a, unsigned long long b)
{
    asm("fma.rn.f32x2 %0, %1, %2, %0;" : "+l"(acc) : "l"(a), "l"(b));
}

// ---------------------------------------------------------------------------
// Logits: L[b][v] = sum_d z[b][d] * Wv[d][v] + bv[v]
// ---------------------------------------------------------------------------
__global__ __launch_bounds__(256, 2) void logits_kernel(
    const float* __restrict__ z, const float* __restrict__ Wv,
    const float* __restrict__ bv, float* __restrict__ L)
{
    __shared__ float sS[BT][64];
    __shared__ float sWv[64][VT];

    const int tid = threadIdx.x;
    const int v0  = blockIdx.x * VT;
    const int b0  = blockIdx.y * BT;
    const int vb  = tid & 31;
    const int bg  = tid >> 5;

    unsigned long long acc[4][2];
    #pragma unroll
    for (int i = 0; i < 4; ++i) { acc[i][0] = 0ull; acc[i][1] = 0ull; }

    for (int slab = 0; slab < DIM / 64; ++slab) {
        const int d0 = slab * 64;
        __syncthreads();
        for (int idx = tid; idx < BT * 64; idx += 256)
            sS[idx >> 6][idx & 63] = z[(size_t)(b0 + (idx >> 6)) * DIM + d0 + (idx & 63)];
        for (int idx = tid; idx < 64 * VT; idx += 256)
            sWv[idx >> 7][idx & 127] = Wv[(size_t)(d0 + (idx >> 7)) * VOCAB + v0 + (idx & 127)];
        __syncthreads();

        #pragma unroll 4
        for (int d = 0; d < 64; ++d) {
            const ulonglong2 w2 = *(const ulonglong2*)&sWv[d][vb * 4];
            #pragma unroll
            for (int i = 0; i < 4; ++i) {
                const float u = sS[bg * 4 + i][d];
                const unsigned long long uu = pack2(u, u);
                ffma2(acc[i][0], uu, w2.x);
                ffma2(acc[i][1], uu, w2.y);
            }
        }
    }

    const float4 bvv = *(const float4*)&bv[v0 + vb * 4];
    #pragma unroll
    for (int i = 0; i < 4; ++i) {
        const float2 p0 = unpack2(acc[i][0]);
        const float2 p1 = unpack2(acc[i][1]);
        float4 r = make_float4(p0.x + bvv.x, p0.y + bvv.y,
                               p1.x + bvv.z, p1.y + bvv.w);
        *(float4*)&L[(size_t)(b0 + bg * 4 + i) * VOCAB + v0 + vb * 4] = r;
    }
}

// ---------------------------------------------------------------------------
// In-place log_softmax over each row of L [BATCH][VOCAB]
// ---------------------------------------------------------------------------
__global__ __launch_bounds__(256) void logsoftmax_kernel(float* __restrict__ L)
{
    const int b   = blockIdx.x;
    const int tid = threadIdx.x;
    float* row = L + (size_t)b * VOCAB;
    __shared__ float red[8];

    float m = -1e30f;
    for (int i = tid * 4; i < VOCAB; i += 1024) {
        const float4 v = *(const float4*)&row[i];
        m = fmaxf(m, fmaxf(fmaxf(v.x, v.y), fmaxf(v.z, v.w)));
    }
    #pragma unroll
    for (int o = 16; o; o >>= 1) m = fmaxf(m, __shfl_xor_sync(0xffffffffu, m, o));
    if ((tid & 31) == 0) red[tid >> 5] = m;
    __syncthreads();
    float M = red[0];
    #pragma unroll
    for (int j = 1; j < 8; ++j) M = fmaxf(M, red[j]);
    __syncthreads();

    float s = 0.f;
    for (int i = tid * 4; i < VOCAB; i += 1024) {
        const float4 v = *(const float4*)&row[i];
        s += expf(v.x - M) + expf(v.y - M) + expf(v.z - M) + expf(v.w - M);
    }
    #pragma unroll
    for (int o = 16; o; o >>= 1) s += __shfl_xor_sync(0xffffffffu, s, o);
    if ((tid & 31) == 0) red[tid >> 5] = s;
    __syncthreads();
    float S = 0.f;
    #pragma unroll
    for (int j = 0; j < 8; ++j) S += red[j];
    const float lse = M + logf(S);

    for (int i = tid * 4; i < VOCAB; i += 1024) {
        float4 v = *(const float4*)&row[i];
        v.x -= lse; v.y -= lse; v.z -= lse; v.w -= lse;
        *(float4*)&row[i] = v;
    }
}

// ---------------------------------------------------------------------------
// kernel_launch — 3 graph nodes
// Inputs: 0 hidden [B,1,D] | 1 tokens [B,T] int | 2 emb_out [V,D] | 3 W_dt [2D,D]
//         4 b_dt [D] | 5 gamma [D] | 6 beta [D] | 7 W_v [D,V] | 8 b_v [V]
// Output: [ z (B*D) | y (B*V) ] f32
// ---------------------------------------------------------------------------
extern "C" void kernel_launch(void* const* d_in, const int* in_sizes, int n_in,
                              void* d_out, int out_size)
{
    const float* hidden = (const float*)d_in[0];
    const int*   tok    = (const int*)  d_in[1];
    const float* emb    = (const float*)d_in[2];
    const float* Wdt    = (const float*)d_in[3];
    const float* bdt    = (const float*)d_in[4];
    const float* gamma  = (const float*)d_in[5];
    const float* beta   = (const float*)d_in[6];
    const float* Wv     = (const float*)d_in[7];
    const float* bv     = (const float*)d_in[8];

    float* zout = (float*)d_out;
    float* yout = zout + (size_t)BATCH * DIM;

    cudaFuncSetAttribute(rnn_persistent,
                         cudaFuncAttributeMaxDynamicSharedMemorySize, SMEM_BYTES);

    rnn_persistent<<<NCTA, 256, SMEM_BYTES>>>(hidden, tok, emb, Wdt, bdt, gamma, beta, zout);
    logits_kernel<<<dim3(VOCAB / VT, BATCH / BT), 256>>>(zout, Wv, bv, yout);
    logsoftmax_kernel<<<BATCH, 256>>>(yout);
}

// round 13
// speedup vs baseline: 1.0216x; 1.0216x over previous
#include <cuda_runtime.h>
#include <cuda_bf16.h>
#include <math.h>
#include <stdint.h>

// Problem constants
#define BATCH 256
#define TLEN  512
#define DIM   1024
#define VOCAB 32000

// Persistent tiling: 128 CTAs (1/SM); CTA bid -> (kc = bid>>4 of 8, nc = bid&15 of 16)
//   GEMM tile: 256 batch rows x 64 cols x 128 K.  LN rows: b = 2*bid + (tid>>7).
#define NK 8
#define NN 16
#define KT 128
#define NT 64
#define NCTA 128
#define KC 64                 // K-chunk per cp.async stage (2 per step)

// Logits tiling
#define VT 128
#define BT 32

// SMEM layout (dynamic):
//  sW: [2 splits][128 k][72 bf16]  stride 144B -> 2 x 18432 = 36864 B
//  sA: [2 chunks][2 splits][256 m][72 bf16] stride 144B -> per split 36864 B
#define SM_W    0
#define W_SPL   18432u
#define ASTRIDE 144u
#define SM_A    36864
#define ASPL    36864u        // per-split (256 rows x 144B)
#define ACH     73728u        // per-chunk (2 splits)
#define SMEM_BYTES (36864 + 2 * 73728)   // 184320

// ---------------------------------------------------------------------------
// Device scratch (static — no cudaMalloc allowed)
// ---------------------------------------------------------------------------
__device__ float         g_P[NK][BATCH][DIM];     // partial sums
__device__ __nv_bfloat16 g_Uhi[BATCH][DIM], g_Ulo[BATCH][DIM];  // u row-major, split
__device__ __nv_bfloat16 g_Hhi[BATCH][DIM], g_Hlo[BATCH][DIM];  // hidden row-major, split

// Hierarchical barrier state (monotonic counters; padded to distinct L2 lines)
struct __align__(128) PadCtr { unsigned v; unsigned pad[31]; };
__device__ PadCtr  g_grp[8];        // per-group arrival counters (16 CTAs each)
__device__ PadCtr  g_root;          // root counter (8 group leaders)
__device__ unsigned g_gen = 0;      // release generation

// ---------------------------------------------------------------------------
// PTX helpers
// ---------------------------------------------------------------------------
__device__ __forceinline__ uint32_t smem_u32(const void* p) {
    uint32_t a;
    asm("{ .reg .u64 t; cvta.to.shared.u64 t, %1; cvt.u32.u64 %0, t; }" : "=r"(a) : "l"(p));
    return a;
}
__device__ __forceinline__ void cp_async16(uint32_t dst, const void* src) {
    asm volatile("cp.async.cg.shared.global [%0], [%1], 16;" :: "r"(dst), "l"(src) : "memory");
}
#define CP_COMMIT() asm volatile("cp.async.commit_group;" ::: "memory")
#define CP_WAIT(n)  asm volatile("cp.async.wait_group %0;" :: "n"(n) : "memory")

// non-trans x4 (A fragment, row-major [m][k])
__device__ __forceinline__ void ldm_x4(uint32_t* r, uint32_t addr) {
    asm volatile("ldmatrix.sync.aligned.m8n8.x4.shared.b16 {%0,%1,%2,%3}, [%4];"
                 : "=r"(r[0]), "=r"(r[1]), "=r"(r[2]), "=r"(r[3]) : "r"(addr));
}
// trans x2 (B fragment from W [k][n])
__device__ __forceinline__ void ldm_x2_t(uint32_t* r, uint32_t addr) {
    asm volatile("ldmatrix.sync.aligned.m8n8.x2.trans.shared.b16 {%0,%1}, [%2];"
                 : "=r"(r[0]), "=r"(r[1]) : "r"(addr));
}
__device__ __forceinline__ void mma_bf16(float* c, const uint32_t* a, const uint32_t* b) {
    asm volatile(
        "mma.sync.aligned.m16n8k16.row.col.f32.bf16.bf16.f32 "
        "{%0,%1,%2,%3}, {%4,%5,%6,%7}, {%8,%9}, {%0,%1,%2,%3};"
        : "+f"(c[0]), "+f"(c[1]), "+f"(c[2]), "+f"(c[3])
        : "r"(a[0]), "r"(a[1]), "r"(a[2]), "r"(a[3]), "r"(b[0]), "r"(b[1]));
}
__device__ __forceinline__ uint32_t pack_bf16x2(float a, float b) {
    const __nv_bfloat16 ba = __float2bfloat16(a);
    const __nv_bfloat16 bb = __float2bfloat16(b);
    return (uint32_t)__bfloat16_as_ushort(ba) | ((uint32_t)__bfloat16_as_ushort(bb) << 16);
}
// split 8 fp32 channels -> bf16 hi/lo, store as 2x16B (.cg)
__device__ __forceinline__ void split_store8(__nv_bfloat16* hp, __nv_bfloat16* lp,
                                             const float* v)
{
    uint32_t h[4], l[4];
    #pragma unroll
    for (int q = 0; q < 4; ++q) {
        const float a = v[2*q], b = v[2*q+1];
        h[q] = pack_bf16x2(a, b);
        const float la = a - __bfloat162float(__float2bfloat16(a));
        const float lb = b - __bfloat162float(__float2bfloat16(b));
        l[q] = pack_bf16x2(la, lb);
    }
    __stcg((uint4*)hp, make_uint4(h[0], h[1], h[2], h[3]));
    __stcg((uint4*)lp, make_uint4(l[0], l[1], l[2], l[3]));
}

// ---------------------------------------------------------------------------
// Hierarchical grid barrier: 8 groups x 16 CTAs -> root -> release.
// Monotonic counters; gbase snapshots the generation at kernel entry so graph
// replays work without resets. m is the per-CTA barrier ordinal (1-based).
// ---------------------------------------------------------------------------
__device__ __forceinline__ void grid_barrier(unsigned& m, unsigned gbase,
                                             int grp, int tid)
{
    __threadfence();
    __syncthreads();
    ++m;
    if (tid == 0) {
        const unsigned target = gbase + m;
        const unsigned old = atomicAdd(&g_grp[grp].v, 1u);
        if (old == target * 16u - 1u) {           // group leader
            const unsigned r = atomicAdd(&g_root.v, 1u);
            if (r == target * 8u - 1u) {          // root leader
                __threadfence();
                *(volatile unsigned*)&g_gen = target;   // release
            }
        }
        while (*(volatile unsigned*)&g_gen < target) { }
        __threadfence();
    }
    __syncthreads();
}

// ---------------------------------------------------------------------------
// W tile load: fp32 Wdt -> smem bf16 hi/lo, [k][n] stride 144B
// ---------------------------------------------------------------------------
__device__ __forceinline__ void load_w(char* smp, const float* __restrict__ Wdt,
                                       int half, int k0, int n0, int tid)
{
    #pragma unroll
    for (int t = 0; t < 32; ++t) {
        const int i = tid + t * 256;      // 0..8191
        const int k = i >> 6;
        const int n = i & 63;
        const float v = Wdt[(size_t)(half * DIM + k0 + k) * DIM + n0 + n];
        const __nv_bfloat16 hi = __float2bfloat16(v);
        const __nv_bfloat16 lo = __float2bfloat16(v - __bfloat162float(hi));
        *(__nv_bfloat16*)(smp + SM_W + (uint32_t)k * ASTRIDE + (uint32_t)n * 2u) = hi;
        *(__nv_bfloat16*)(smp + SM_W + W_SPL + (uint32_t)k * ASTRIDE + (uint32_t)n * 2u) = lo;
    }
}

// cp.async one 64-k chunk of A (hi+lo): 256 rows x 128B x 2 splits = 4096 x 16B
__device__ __forceinline__ void issue_chunk(uint32_t sa_base,
    const __nv_bfloat16* __restrict__ srchi, const __nv_bfloat16* __restrict__ srclo,
    int kglob, int tid)
{
    #pragma unroll
    for (int t = 0; t < 16; ++t) {
        const int i  = tid + t * 256;     // 0..4095
        const int sp = i >> 11;           // 0..1 (2048 transfers per split)
        const int r  = (i >> 3) & 255;    // row 0..255
        const int c  = i & 7;             // 16B column; 8 cols x 16B = 128B = 64 bf16
        const __nv_bfloat16* src = (sp ? srclo : srchi) + (size_t)r * DIM + kglob + c * 8;
        const uint32_t dst = sa_base + (uint32_t)sp * ASPL + (uint32_t)r * ASTRIDE + (uint32_t)c * 16u;
        cp_async16(dst, src);
    }
    CP_COMMIT();
}

// ---------------------------------------------------------------------------
// Compute one 64-k chunk: 4 ksteps x (2 m-tiles x 8 n-tiles x 3 split products)
// A row-major [m][k] stride 144B (non-trans); W [k][n] stride 144B (trans).
// ---------------------------------------------------------------------------
__device__ __forceinline__ void compute_chunk(uint32_t abase, uint32_t wbase, int c,
                                              float acc[2][8][4], int lane, int wid)
{
    #pragma unroll
    for (int ks = 0; ks < 4; ++ks) {
        // B fragments (k-row within the CTA's full K=128 W tile)
        uint32_t bh[8][2], bl[8][2];
        const uint32_t krow_b = (uint32_t)(c * KC + ks * 16 + (lane & 15));
        #pragma unroll
        for (int nt = 0; nt < 8; ++nt) {
            ldm_x2_t(bh[nt], wbase + 0u    + krow_b * ASTRIDE + (uint32_t)nt * 16u);
            ldm_x2_t(bl[nt], wbase + W_SPL + krow_b * ASTRIDE + (uint32_t)nt * 16u);
        }
        // A fragments (within-chunk k 0..63)
        const uint32_t arow = (uint32_t)(wid * 32 + (lane & 15));
        const uint32_t acol = (uint32_t)(ks * 32 + (lane >> 4) * 16);
        uint32_t ah[2][4], al[2][4];
        #pragma unroll
        for (int mt = 0; mt < 2; ++mt) {
            const uint32_t off = (arow + (uint32_t)mt * 16u) * ASTRIDE + acol;
            ldm_x4(ah[mt], abase + off);
            ldm_x4(al[mt], abase + ASPL + off);
        }
        #pragma unroll
        for (int mt = 0; mt < 2; ++mt)
            #pragma unroll
            for (int nt = 0; nt < 8; ++nt) {
                mma_bf16(acc[mt][nt], ah[mt], bh[nt]);
                mma_bf16(acc[mt][nt], ah[mt], bl[nt]);
                mma_bf16(acc[mt][nt], al[mt], bh[nt]);
            }
    }
}

// ---------------------------------------------------------------------------
// One full step GEMM: P[kc][256 b][n0..n0+63] over K [k0, k0+128)
// Both 64-k chunks issued up front; only 2 waits/syncs per step.
// ---------------------------------------------------------------------------
__device__ __forceinline__ void gemm_step_mma(char* smp, uint32_t base,
    const __nv_bfloat16* __restrict__ srchi, const __nv_bfloat16* __restrict__ srclo,
    int k0, int n0, int kc, int tid)
{
    const int lane = tid & 31, wid = tid >> 5;
    float acc[2][8][4];
    #pragma unroll
    for (int mt = 0; mt < 2; ++mt)
        #pragma unroll
        for (int nt = 0; nt < 8; ++nt)
            #pragma unroll
            for (int q = 0; q < 4; ++q) acc[mt][nt][q] = 0.f;

    const uint32_t a0 = base + SM_A;
    const uint32_t a1 = base + SM_A + ACH;
    const uint32_t wb = base + SM_W;

    issue_chunk(a0, srchi, srclo, k0 + 0 * KC, tid);
    issue_chunk(a1, srchi, srclo, k0 + 1 * KC, tid);

    CP_WAIT(1); __syncthreads();
    compute_chunk(a0, wb, 0, acc, lane, wid);
    CP_WAIT(0); __syncthreads();
    compute_chunk(a1, wb, 1, acc, lane, wid);

    // store accumulators -> g_P[kc] (warp wid owns rows wid*32..+31)
    const int r4 = lane >> 2, c2 = (lane & 3) * 2;
    #pragma unroll
    for (int mt = 0; mt < 2; ++mt)
        #pragma unroll
        for (int nt = 0; nt < 8; ++nt) {
            const int r0 = wid * 32 + mt * 16 + r4;
            const int cc = n0 + nt * 8 + c2;
            __stcg((float2*)&g_P[kc][r0][cc],     make_float2(acc[mt][nt][0], acc[mt][nt][1]));
            __stcg((float2*)&g_P[kc][r0 + 8][cc], make_float2(acc[mt][nt][2], acc[mt][nt][3]));
        }
}

// ---------------------------------------------------------------------------
// Persistent scan kernel: init + c precompute + 512 x (HMMA GEMM, LN)
// ---------------------------------------------------------------------------
__global__ __launch_bounds__(256) void rnn_persistent(
    const float* __restrict__ hidden, const int* __restrict__ tok,
    const float* __restrict__ emb,    const float* __restrict__ Wdt,
    const float* __restrict__ bdt,    const float* __restrict__ gamma,
    const float* __restrict__ beta,   float* __restrict__ zout)
{
    extern __shared__ char smp[];
    const uint32_t base = smem_u32(smp);
    __shared__ float red[2][2][4];   // [row][stat][warp-of-row]

    const int tid = threadIdx.x;
    const int bid = blockIdx.x;
    const int nc = bid & 15, kc = bid >> 4;
    const int n0 = nc * NT,  k0 = kc * KT;
    const int grp = bid >> 4;        // barrier group (16 CTAs each)

    // Barrier bookkeeping (monotonic; replay-safe via gbase snapshot)
    unsigned barm = 0;
    const unsigned gbase = *(volatile unsigned*)&g_gen;

    // LN role: 2 rows per CTA
    const int row_sel = tid >> 7;
    const int b  = bid * 2 + row_sel;
    const int lt = tid & 127;
    const int d0 = lt * 8;
    const int wr = (tid >> 5) & 3;

    // ---- init: row-major bf16 splits of hidden and u0 (8 channels/thread) ----
    float ur[8], gm[8], bt[8];
    {
        const int tk0 = tok[(size_t)b * TLEN];
        float hv[8];
        const float4 h0 = *(const float4*)&hidden[(size_t)b * DIM + d0];
        const float4 h1 = *(const float4*)&hidden[(size_t)b * DIM + d0 + 4];
        hv[0]=h0.x; hv[1]=h0.y; hv[2]=h0.z; hv[3]=h0.w;
        hv[4]=h1.x; hv[5]=h1.y; hv[6]=h1.z; hv[7]=h1.w;
        const float4 u0 = *(const float4*)&emb[(size_t)tk0 * DIM + d0];
        const float4 u1 = *(const float4*)&emb[(size_t)tk0 * DIM + d0 + 4];
        ur[0]=u0.x; ur[1]=u0.y; ur[2]=u0.z; ur[3]=u0.w;
        ur[4]=u1.x; ur[5]=u1.y; ur[6]=u1.z; ur[7]=u1.w;
        split_store8(&g_Hhi[b][d0], &g_Hlo[b][d0], hv);
        split_store8(&g_Uhi[b][d0], &g_Ulo[b][d0], ur);
        const float4 g0 = *(const float4*)&gamma[d0];
        const float4 g1 = *(const float4*)&gamma[d0 + 4];
        gm[0]=g0.x; gm[1]=g0.y; gm[2]=g0.z; gm[3]=g0.w;
        gm[4]=g1.x; gm[5]=g1.y; gm[6]=g1.z; gm[7]=g1.w;
        const float4 b0 = *(const float4*)&beta[d0];
        const float4 b1 = *(const float4*)&beta[d0 + 4];
        bt[0]=b0.x; bt[1]=b0.y; bt[2]=b0.z; bt[3]=b0.w;
        bt[4]=b1.x; bt[5]=b1.y; bt[6]=b1.z; bt[7]=b1.w;
    }

    // ---- c = hidden @ W_bot + b_dt ----
    load_w(smp, Wdt, 1, k0, n0, tid);
    grid_barrier(barm, gbase, grp, tid);    // H/U splits visible everywhere
    gemm_step_mma(smp, base, &g_Hhi[0][0], &g_Hlo[0][0], k0, n0, kc, tid);
    grid_barrier(barm, gbase, grp, tid);    // g_P complete

    float cre[8];
    {
        #pragma unroll
        for (int j = 0; j < 8; ++j) cre[j] = 0.f;
        #pragma unroll
        for (int j = 0; j < NK; ++j) {
            const float4 p0 = __ldcg((const float4*)&g_P[j][b][d0]);
            const float4 p1 = __ldcg((const float4*)&g_P[j][b][d0 + 4]);
            cre[0] += p0.x; cre[1] += p0.y; cre[2] += p0.z; cre[3] += p0.w;
            cre[4] += p1.x; cre[5] += p1.y; cre[6] += p1.z; cre[7] += p1.w;
        }
        const float4 bd0 = *(const float4*)&bdt[d0];
        const float4 bd1 = *(const float4*)&bdt[d0 + 4];
        cre[0]+=bd0.x; cre[1]+=bd0.y; cre[2]+=bd0.z; cre[3]+=bd0.w;
        cre[4]+=bd1.x; cre[5]+=bd1.y; cre[6]+=bd1.z; cre[7]+=bd1.w;
    }

    __syncthreads();
    load_w(smp, Wdt, 0, k0, n0, tid);   // W_top, persistent for the scan
    grid_barrier(barm, gbase, grp, tid);    // P consumed before step 0 overwrites

    // ---- scan ----
    for (int t = 0; t < TLEN; ++t) {
        // prefetch next-token embedding
        float ev[8];
        if (t < TLEN - 1) {
            const int tkn = tok[(size_t)b * TLEN + t + 1];
            const float4 e0 = *(const float4*)&emb[(size_t)tkn * DIM + d0];
            const float4 e1 = *(const float4*)&emb[(size_t)tkn * DIM + d0 + 4];
            ev[0]=e0.x; ev[1]=e0.y; ev[2]=e0.z; ev[3]=e0.w;
            ev[4]=e1.x; ev[5]=e1.y; ev[6]=e1.z; ev[7]=e1.w;
        }

        gemm_step_mma(smp, base, &g_Uhi[0][0], &g_Ulo[0][0], k0, n0, kc, tid);
        grid_barrier(barm, gbase, grp, tid);

        // LN: y = C + U + sum_j P[j]
        float y[8];
        #pragma unroll
        for (int j = 0; j < 8; ++j) y[j] = cre[j] + ur[j];
        #pragma unroll
        for (int j = 0; j < NK; ++j) {
            const float4 p0 = __ldcg((const float4*)&g_P[j][b][d0]);
            const float4 p1 = __ldcg((const float4*)&g_P[j][b][d0 + 4]);
            y[0] += p0.x; y[1] += p0.y; y[2] += p0.z; y[3] += p0.w;
            y[4] += p1.x; y[5] += p1.y; y[6] += p1.z; y[7] += p1.w;
        }

        float s1 = 0.f, s2 = 0.f;
        #pragma unroll
        for (int j = 0; j < 8; ++j) { s1 += y[j]; s2 += y[j] * y[j]; }
        #pragma unroll
        for (int o = 16; o; o >>= 1) {
            s1 += __shfl_xor_sync(0xffffffffu, s1, o);
            s2 += __shfl_xor_sync(0xffffffffu, s2, o);
        }
        if ((tid & 31) == 0) { red[row_sel][0][wr] = s1; red[row_sel][1][wr] = s2; }
        __syncthreads();
        float t1 = 0.f, t2 = 0.f;
        #pragma unroll
        for (int j = 0; j < 4; ++j) {
            t1 += red[row_sel][0][j];
            t2 += red[row_sel][1][j];
        }
        __syncthreads();

        const float mean = t1 * (1.f / DIM);
        const float var  = t2 * (1.f / DIM) - mean * mean;
        const float rstd = rsqrtf(var + 1e-5f);

        float sv[8];
        #pragma unroll
        for (int j = 0; j < 8; ++j)
            sv[j] = (y[j] - mean) * rstd * gm[j] + bt[j];

        if (t < TLEN - 1) {
            float un[8];
            #pragma unroll
            for (int j = 0; j < 8; ++j) { un[j] = sv[j] + ev[j]; ur[j] = un[j]; }
            split_store8(&g_Uhi[b][d0], &g_Ulo[b][d0], un);
        } else {
            *(float4*)&zout[(size_t)b * DIM + d0] =
                make_float4(sv[0], sv[1], sv[2], sv[3]);
            *(float4*)&zout[(size_t)b * DIM + d0 + 4] =
                make_float4(sv[4], sv[5], sv[6], sv[7]);
        }
        grid_barrier(barm, gbase, grp, tid);
    }
}

// ---------------------------------------------------------------------------
// Packed f32x2 helpers (logits kernel)
// ---------------------------------------------------------------------------
__device__ __forceinline__ unsigned long long pack2(float lo, float hi)
{
    unsigned long long r;
    asm("mov.b64 %0, {%1, %2};" : "=l"(r) : "f"(lo), "f"(hi));
    return r;
}
__device__ __forceinline__ float2 unpack2(unsigned long long v)
{
    float2 r;
    asm("mov.b64 {%0, %1}, %2;" : "=f"(r.x), "=f"(r.y) : "l"(v));
    return r;
}
__device__ __forceinline__ void ffma2(unsigned long long& acc,
                                      unsigned long long a, unsigned long long b)
{
    asm("fma.rn.f32x2 %0, %1, %2, %0;" : "+l"(acc) : "l"(a), "l"(b));
}

// ---------------------------------------------------------------------------
// Logits: L[b][v] = sum_d z[b][d] * Wv[d][v] + bv[v]
// ---------------------------------------------------------------------------
__global__ __launch_bounds__(256, 2) void logits_kernel(
    const float* __restrict__ z, const float* __restrict__ Wv,
    const float* __restrict__ bv, float* __restrict__ L)
{
    __shared__ float sS[BT][64];
    __shared__ float sWv[64][VT];

    const int tid = threadIdx.x;
    const int v0  = blockIdx.x * VT;
    const int b0  = blockIdx.y * BT;
    const int vb  = tid & 31;
    const int bg  = tid >> 5;

    unsigned long long acc[4][2];
    #pragma unroll
    for (int i = 0; i < 4; ++i) { acc[i][0] = 0ull; acc[i][1] = 0ull; }

    for (int slab = 0; slab < DIM / 64; ++slab) {
        const int d0 = slab * 64;
        __syncthreads();
        for (int idx = tid; idx < BT * 64; idx += 256)
            sS[idx >> 6][idx & 63] = z[(size_t)(b0 + (idx >> 6)) * DIM + d0 + (idx & 63)];
        for (int idx = tid; idx < 64 * VT; idx += 256)
            sWv[idx >> 7][idx & 127] = Wv[(size_t)(d0 + (idx >> 7)) * VOCAB + v0 + (idx & 127)];
        __syncthreads();

        #pragma unroll 4
        for (int d = 0; d < 64; ++d) {
            const ulonglong2 w2 = *(const ulonglong2*)&sWv[d][vb * 4];
            #pragma unroll
            for (int i = 0; i < 4; ++i) {
                const float u = sS[bg * 4 + i][d];
                const unsigned long long uu = pack2(u, u);
                ffma2(acc[i][0], uu, w2.x);
                ffma2(acc[i][1], uu, w2.y);
            }
        }
    }

    const float4 bvv = *(const float4*)&bv[v0 + vb * 4];
    #pragma unroll
    for (int i = 0; i < 4; ++i) {
        const float2 p0 = unpack2(acc[i][0]);
        const float2 p1 = unpack2(acc[i][1]);
        float4 r = make_float4(p0.x + bvv.x, p0.y + bvv.y,
                               p1.x + bvv.z, p1.y + bvv.w);
        *(float4*)&L[(size_t)(b0 + bg * 4 + i) * VOCAB + v0 + vb * 4] = r;
    }
}

// ---------------------------------------------------------------------------
// In-place log_softmax over each row of L [BATCH][VOCAB]
// ---------------------------------------------------------------------------
__global__ __launch_bounds__(256) void logsoftmax_kernel(float* __restrict__ L)
{
    const int b   = blockIdx.x;
    const int tid = threadIdx.x;
    float* row = L + (size_t)b * VOCAB;
    __shared__ float red[8];

    float m = -1e30f;
    for (int i = tid * 4; i < VOCAB; i += 1024) {
        const float4 v = *(const float4*)&row[i];
        m = fmaxf(m, fmaxf(fmaxf(v.x, v.y), fmaxf(v.z, v.w)));
    }
    #pragma unroll
    for (int o = 16; o; o >>= 1) m = fmaxf(m, __shfl_xor_sync(0xffffffffu, m, o));
    if ((tid & 31) == 0) red[tid >> 5] = m;
    __syncthreads();
    float M = red[0];
    #pragma unroll
    for (int j = 1; j < 8; ++j) M = fmaxf(M, red[j]);
    __syncthreads();

    float s = 0.f;
    for (int i = tid * 4; i < VOCAB; i += 1024) {
        const float4 v = *(const float4*)&row[i];
        s += expf(v.x - M) + expf(v.y - M) + expf(v.z - M) + expf(v.w - M);
    }
    #pragma unroll
    for (int o = 16; o; o >>= 1) s += __shfl_xor_sync(0xffffffffu, s, o);
    if ((tid & 31) == 0) red[tid >> 5] = s;
    __syncthreads();
    float S = 0.f;
    #pragma unroll
    for (int j = 0; j < 8; ++j) S += red[j];
    const float lse = M + logf(S);

    for (int i = tid * 4; i < VOCAB; i += 1024) {
        float4 v = *(const float4*)&row[i];
        v.x -= lse; v.y -= lse; v.z -= lse; v.w -= lse;
        *(float4*)&row[i] = v;
    }
}

// ---------------------------------------------------------------------------
// kernel_launch — 3 graph nodes
// Inputs: 0 hidden [B,1,D] | 1 tokens [B,T] int | 2 emb_out [V,D] | 3 W_dt [2D,D]
//         4 b_dt [D] | 5 gamma [D] | 6 beta [D] | 7 W_v [D,V] | 8 b_v [V]
// Output: [ z (B*D) | y (B*V) ] f32
// ---------------------------------------------------------------------------
extern "C" void kernel_launch(void* const* d_in, const int* in_sizes, int n_in,
                              void* d_out, int out_size)
{
    const float* hidden = (const float*)d_in[0];
    const int*   tok    = (const int*)  d_in[1];
    const float* emb    = (const float*)d_in[2];
    const float* Wdt    = (const float*)d_in[3];
    const float* bdt    = (const float*)d_in[4];
    const float* gamma  = (const float*)d_in[5];
    const float* beta   = (const float*)d_in[6];
    const float* Wv     = (const float*)d_in[7];
    const float* bv     = (const float*)d_in[8];

    float* zout = (float*)d_out;
    float* yout = zout + (size_t)BATCH * DIM;

    cudaFuncSetAttribute(rnn_persistent,
                         cudaFuncAttributeMaxDynamicSharedMemorySize, SMEM_BYTES);

    rnn_persistent<<<NCTA, 256, SMEM_BYTES>>>(hidden, tok, emb, Wdt, bdt, gamma, beta, zout);
    logits_kernel<<<dim3(VOCAB / VT, BATCH / BT), 256>>>(zout, Wv, bv, yout);
    logsoftmax_kernel<<<BATCH, 256>>>(yout);
}

// round 14
// speedup vs baseline: 1.1612x; 1.1367x over previous
#include <cuda_runtime.h>
#include <cuda_bf16.h>
#include <math.h>
#include <stdint.h>

// Problem constants
#define BATCH 256
#define TLEN  512
#define DIM   1024
#define VOCAB 32000

// Persistent tiling: 128 CTAs (1/SM);
//   bid -> mb = bid&3 (64-row block), nc = (bid>>2)&7 (128-col tile), kc = bid>>5 (K=256 slab)
//   GEMM tile per CTA: 64 batch rows x 128 cols x 256 K.  LN rows: b = 2*bid + (tid>>7).
#define NK 4
#define KT 256
#define NT 128
#define NCTA 128

// Logits tiling
#define VT 128
#define BT 32

// SMEM layout (dynamic):
//  sW: [2 splits][256 k][136 bf16] stride 272B -> per split 69632, total 139264
//  sA: [2 splits][64 m][264 bf16]  stride 528B -> per split 33792, total 67584
#define SM_W    0
#define W_SPL   69632u
#define WSTRIDE 272u
#define SM_A    139264
#define ASPL    33792u
#define ASTRIDE 528u
#define SMEM_BYTES (139264 + 67584)   // 206848

// ---------------------------------------------------------------------------
// Device scratch (static — no cudaMalloc allowed)
// ---------------------------------------------------------------------------
__device__ float         g_P[NK][BATCH][DIM];     // partial sums (4 MB)
__device__ __nv_bfloat16 g_Uhi[BATCH][DIM], g_Ulo[BATCH][DIM];  // u row-major, split
__device__ __nv_bfloat16 g_Hhi[BATCH][DIM], g_Hlo[BATCH][DIM];  // hidden row-major, split
__device__ unsigned g_bar_arrive = 0;
__device__ unsigned g_bar_gen    = 0;

// ---------------------------------------------------------------------------
// PTX helpers
// ---------------------------------------------------------------------------
__device__ __forceinline__ uint32_t smem_u32(const void* p) {
    uint32_t a;
    asm("{ .reg .u64 t; cvta.to.shared.u64 t, %1; cvt.u32.u64 %0, t; }" : "=r"(a) : "l"(p));
    return a;
}
__device__ __forceinline__ void cp_async16(uint32_t dst, const void* src) {
    asm volatile("cp.async.cg.shared.global [%0], [%1], 16;" :: "r"(dst), "l"(src) : "memory");
}
#define CP_COMMIT() asm volatile("cp.async.commit_group;" ::: "memory")
#define CP_WAIT(n)  asm volatile("cp.async.wait_group %0;" :: "n"(n) : "memory")

// non-trans x4 (A fragment, row-major [m][k])
__device__ __forceinline__ void ldm_x4(uint32_t* r, uint32_t addr) {
    asm volatile("ldmatrix.sync.aligned.m8n8.x4.shared.b16 {%0,%1,%2,%3}, [%4];"
                 : "=r"(r[0]), "=r"(r[1]), "=r"(r[2]), "=r"(r[3]) : "r"(addr));
}
// trans x2 (B fragment from W [k][n])
__device__ __forceinline__ void ldm_x2_t(uint32_t* r, uint32_t addr) {
    asm volatile("ldmatrix.sync.aligned.m8n8.x2.trans.shared.b16 {%0,%1}, [%2];"
                 : "=r"(r[0]), "=r"(r[1]) : "r"(addr));
}
__device__ __forceinline__ void mma_bf16(float* c, const uint32_t* a, const uint32_t* b) {
    asm volatile(
        "mma.sync.aligned.m16n8k16.row.col.f32.bf16.bf16.f32 "
        "{%0,%1,%2,%3}, {%4,%5,%6,%7}, {%8,%9}, {%0,%1,%2,%3};"
        : "+f"(c[0]), "+f"(c[1]), "+f"(c[2]), "+f"(c[3])
        : "r"(a[0]), "r"(a[1]), "r"(a[2]), "r"(a[3]), "r"(b[0]), "r"(b[1]));
}
__device__ __forceinline__ uint32_t pack_bf16x2(float a, float b) {
    const __nv_bfloat16 ba = __float2bfloat16(a);
    const __nv_bfloat16 bb = __float2bfloat16(b);
    return (uint32_t)__bfloat16_as_ushort(ba) | ((uint32_t)__bfloat16_as_ushort(bb) << 16);
}
// split 8 fp32 channels -> bf16 hi/lo, store as 2x16B (.cg)
__device__ __forceinline__ void split_store8(__nv_bfloat16* hp, __nv_bfloat16* lp,
                                             const float* v)
{
    uint32_t h[4], l[4];
    #pragma unroll
    for (int q = 0; q < 4; ++q) {
        const float a = v[2*q], b = v[2*q+1];
        h[q] = pack_bf16x2(a, b);
        const float la = a - __bfloat162float(__float2bfloat16(a));
        const float lb = b - __bfloat162float(__float2bfloat16(b));
        l[q] = pack_bf16x2(la, lb);
    }
    __stcg((uint4*)hp, make_uint4(h[0], h[1], h[2], h[3]));
    __stcg((uint4*)lp, make_uint4(l[0], l[1], l[2], l[3]));
}

// ---------------------------------------------------------------------------
// Grid-wide barrier (sense-reversing; 128 CTAs, 1/SM) — R11-proven version
// ---------------------------------------------------------------------------
__device__ __forceinline__ void grid_barrier()
{
    __threadfence();
    __syncthreads();
    if (threadIdx.x == 0) {
        unsigned gen = *(volatile unsigned*)&g_bar_gen;
        if (atomicAdd(&g_bar_arrive, 1u) == NCTA - 1u) {
            atomicExch(&g_bar_arrive, 0u);
            __threadfence();
            atomicAdd(&g_bar_gen, 1u);
        } else {
            while (*(volatile unsigned*)&g_bar_gen == gen) { }
        }
        __threadfence();
    }
    __syncthreads();
}

// ---------------------------------------------------------------------------
// W tile load: fp32 Wdt -> smem bf16 hi/lo, [256 k][128 n] stride 272B
// ---------------------------------------------------------------------------
__device__ __forceinline__ void load_w(char* smp, const float* __restrict__ Wdt,
                                       int half, int k0, int n0, int tid)
{
    for (int i = tid; i < KT * NT; i += 256) {     // 32768 elems, 128/thread
        const int k = i >> 7;
        const int n = i & 127;
        const float v = Wdt[(size_t)(half * DIM + k0 + k) * DIM + n0 + n];
        const __nv_bfloat16 hi = __float2bfloat16(v);
        const __nv_bfloat16 lo = __float2bfloat16(v - __bfloat162float(hi));
        *(__nv_bfloat16*)(smp + SM_W + (uint32_t)k * WSTRIDE + (uint32_t)n * 2u) = hi;
        *(__nv_bfloat16*)(smp + SM_W + W_SPL + (uint32_t)k * WSTRIDE + (uint32_t)n * 2u) = lo;
    }
}

// cp.async one K=128 half of A (hi+lo): 64 rows x 256B x 2 splits = 2048 x 16B
// dst column range [g*256, g*256+256) within each 528B row.
__device__ __forceinline__ void issue_half(uint32_t sa_base,
    const __nv_bfloat16* __restrict__ srchi, const __nv_bfloat16* __restrict__ srclo,
    int m0, int kglob, uint32_t dcol, int tid)
{
    #pragma unroll
    for (int t = 0; t < 8; ++t) {
        const int i  = tid + t * 256;     // 0..2047
        const int sp = i >> 10;           // split
        const int r  = (i >> 4) & 63;     // row 0..63
        const int c  = i & 15;            // 16B col 0..15 (256B)
        const __nv_bfloat16* src =
            (sp ? srclo : srchi) + (size_t)(m0 + r) * DIM + kglob + c * 8;
        const uint32_t dst = sa_base + (uint32_t)sp * ASPL
                           + (uint32_t)r * ASTRIDE + dcol + (uint32_t)c * 16u;
        cp_async16(dst, src);
    }
    CP_COMMIT();
}

// ---------------------------------------------------------------------------
// Compute 8 ksteps (one K=128 half): warp (mw = wid&3, nw = wid>>2)
//   handles rows m-local mw*16..+15, cols nw*64..+63 (8 n-tiles).
// A [m][k] stride 528B (non-trans); W [k][n] stride 272B (trans).
// ---------------------------------------------------------------------------
__device__ __forceinline__ void compute_half(uint32_t abase, uint32_t wbase, int ks0,
                                             float acc[8][4], int lane, int mw, int nw)
{
    #pragma unroll
    for (int ks = ks0; ks < ks0 + 8; ++ks) {
        // A fragment (1 m-tile)
        const uint32_t arow = (uint32_t)(mw * 16 + (lane & 15));
        const uint32_t acol = (uint32_t)(ks * 32 + (lane >> 4) * 16);
        uint32_t ah[4], al[4];
        {
            const uint32_t off = arow * ASTRIDE + acol;
            ldm_x4(ah, abase + off);
            ldm_x4(al, abase + ASPL + off);
        }
        const uint32_t krow_b = (uint32_t)(ks * 16 + (lane & 15));
        #pragma unroll
        for (int g = 0; g < 2; ++g) {     // B in 2 groups of 4 n-tiles
            uint32_t bh[4][2], bl[4][2];
            #pragma unroll
            for (int j = 0; j < 4; ++j) {
                const uint32_t nb = (uint32_t)(nw * 128 + (g * 4 + j) * 16);
                ldm_x2_t(bh[j], wbase + 0u    + krow_b * WSTRIDE + nb);
                ldm_x2_t(bl[j], wbase + W_SPL + krow_b * WSTRIDE + nb);
            }
            #pragma unroll
            for (int j = 0; j < 4; ++j) {
                float* a = acc[g * 4 + j];
                mma_bf16(a, ah, bh[j]);
                mma_bf16(a, ah, bl[j]);
                mma_bf16(a, al, bh[j]);
            }
        }
    }
}

// ---------------------------------------------------------------------------
// One full step GEMM: P[kc][m0..m0+63][n0..n0+127] over K [k0, k0+256)
// ---------------------------------------------------------------------------
__device__ __forceinline__ void gemm_step_mma(char* smp, uint32_t base,
    const __nv_bfloat16* __restrict__ srchi, const __nv_bfloat16* __restrict__ srclo,
    int m0, int k0, int n0, int kc, int tid)
{
    const int lane = tid & 31, wid = tid >> 5;
    const int mw = wid & 3, nw = wid >> 2;
    float acc[8][4];
    #pragma unroll
    for (int nt = 0; nt < 8; ++nt)
        #pragma unroll
        for (int q = 0; q < 4; ++q) acc[nt][q] = 0.f;

    const uint32_t ab = base + SM_A;
    const uint32_t wb = base + SM_W;

    issue_half(ab, srchi, srclo, m0, k0 + 0,   0u,   tid);
    issue_half(ab, srchi, srclo, m0, k0 + 128, 256u, tid);

    CP_WAIT(1); __syncthreads();
    compute_half(ab, wb, 0, acc, lane, mw, nw);
    CP_WAIT(0); __syncthreads();
    compute_half(ab, wb, 8, acc, lane, mw, nw);

    // store accumulators -> g_P[kc]
    const int r4 = lane >> 2, c2 = (lane & 3) * 2;
    #pragma unroll
    for (int nt = 0; nt < 8; ++nt) {
        const int r0 = m0 + mw * 16 + r4;
        const int cc = n0 + nw * 64 + nt * 8 + c2;
        __stcg((float2*)&g_P[kc][r0][cc],     make_float2(acc[nt][0], acc[nt][1]));
        __stcg((float2*)&g_P[kc][r0 + 8][cc], make_float2(acc[nt][2], acc[nt][3]));
    }
}

// ---------------------------------------------------------------------------
// Persistent scan kernel: init + c precompute + 512 x (HMMA GEMM, LN)
// ---------------------------------------------------------------------------
__global__ __launch_bounds__(256) void rnn_persistent(
    const float* __restrict__ hidden, const int* __restrict__ tok,
    const float* __restrict__ emb,    const float* __restrict__ Wdt,
    const float* __restrict__ bdt,    const float* __restrict__ gamma,
    const float* __restrict__ beta,   float* __restrict__ zout)
{
    extern __shared__ char smp[];
    const uint32_t base = smem_u32(smp);
    __shared__ float red[2][2][4];   // [row][stat][warp-of-row]

    const int tid = threadIdx.x;
    const int bid = blockIdx.x;
    const int mb = bid & 3, nc = (bid >> 2) & 7, kc = bid >> 5;
    const int m0 = mb * 64, n0 = nc * NT, k0 = kc * KT;

    // LN role: 2 rows per CTA
    const int row_sel = tid >> 7;
    const int b  = bid * 2 + row_sel;
    const int lt = tid & 127;
    const int d0 = lt * 8;
    const int wr = (tid >> 5) & 3;

    // ---- init: row-major bf16 splits of hidden and u0 (8 channels/thread) ----
    float ur[8], gm[8], bt[8];
    {
        const int tk0 = tok[(size_t)b * TLEN];
        float hv[8];
        const float4 h0 = *(const float4*)&hidden[(size_t)b * DIM + d0];
        const float4 h1 = *(const float4*)&hidden[(size_t)b * DIM + d0 + 4];
        hv[0]=h0.x; hv[1]=h0.y; hv[2]=h0.z; hv[3]=h0.w;
        hv[4]=h1.x; hv[5]=h1.y; hv[6]=h1.z; hv[7]=h1.w;
        const float4 u0 = *(const float4*)&emb[(size_t)tk0 * DIM + d0];
        const float4 u1 = *(const float4*)&emb[(size_t)tk0 * DIM + d0 + 4];
        ur[0]=u0.x; ur[1]=u0.y; ur[2]=u0.z; ur[3]=u0.w;
        ur[4]=u1.x; ur[5]=u1.y; ur[6]=u1.z; ur[7]=u1.w;
        split_store8(&g_Hhi[b][d0], &g_Hlo[b][d0], hv);
        split_store8(&g_Uhi[b][d0], &g_Ulo[b][d0], ur);
        const float4 g0 = *(const float4*)&gamma[d0];
        const float4 g1 = *(const float4*)&gamma[d0 + 4];
        gm[0]=g0.x; gm[1]=g0.y; gm[2]=g0.z; gm[3]=g0.w;
        gm[4]=g1.x; gm[5]=g1.y; gm[6]=g1.z; gm[7]=g1.w;
        const float4 b0 = *(const float4*)&beta[d0];
        const float4 b1 = *(const float4*)&beta[d0 + 4];
        bt[0]=b0.x; bt[1]=b0.y; bt[2]=b0.z; bt[3]=b0.w;
        bt[4]=b1.x; bt[5]=b1.y; bt[6]=b1.z; bt[7]=b1.w;
    }

    // ---- c = hidden @ W_bot + b_dt ----
    load_w(smp, Wdt, 1, k0, n0, tid);
    grid_barrier();                     // H/U splits visible everywhere
    gemm_step_mma(smp, base, &g_Hhi[0][0], &g_Hlo[0][0], m0, k0, n0, kc, tid);
    grid_barrier();                     // g_P complete

    float cre[8];
    {
        #pragma unroll
        for (int j = 0; j < 8; ++j) cre[j] = 0.f;
        #pragma unroll
        for (int j = 0; j < NK; ++j) {
            const float4 p0 = __ldcg((const float4*)&g_P[j][b][d0]);
            const float4 p1 = __ldcg((const float4*)&g_P[j][b][d0 + 4]);
            cre[0] += p0.x; cre[1] += p0.y; cre[2] += p0.z; cre[3] += p0.w;
            cre[4] += p1.x; cre[5] += p1.y; cre[6] += p1.z; cre[7] += p1.w;
        }
        const float4 bd0 = *(const float4*)&bdt[d0];
        const float4 bd1 = *(const float4*)&bdt[d0 + 4];
        cre[0]+=bd0.x; cre[1]+=bd0.y; cre[2]+=bd0.z; cre[3]+=bd0.w;
        cre[4]+=bd1.x; cre[5]+=bd1.y; cre[6]+=bd1.z; cre[7]+=bd1.w;
    }

    __syncthreads();
    load_w(smp, Wdt, 0, k0, n0, tid);   // W_top, persistent for the scan
    grid_barrier();                     // P consumed before step 0 overwrites

    // ---- scan ----
    for (int t = 0; t < TLEN; ++t) {
        // prefetch next-token embedding
        float ev[8];
        if (t < TLEN - 1) {
            const int tkn = tok[(size_t)b * TLEN + t + 1];
            const float4 e0 = *(const float4*)&emb[(size_t)tkn * DIM + d0];
            const float4 e1 = *(const float4*)&emb[(size_t)tkn * DIM + d0 + 4];
            ev[0]=e0.x; ev[1]=e0.y; ev[2]=e0.z; ev[3]=e0.w;
            ev[4]=e1.x; ev[5]=e1.y; ev[6]=e1.z; ev[7]=e1.w;
        }

        gemm_step_mma(smp, base, &g_Uhi[0][0], &g_Ulo[0][0], m0, k0, n0, kc, tid);
        grid_barrier();

        // LN: y = C + U + sum_j P[j]
        float y[8];
        #pragma unroll
        for (int j = 0; j < 8; ++j) y[j] = cre[j] + ur[j];
        #pragma unroll
        for (int j = 0; j < NK; ++j) {
            const float4 p0 = __ldcg((const float4*)&g_P[j][b][d0]);
            const float4 p1 = __ldcg((const float4*)&g_P[j][b][d0 + 4]);
            y[0] += p0.x; y[1] += p0.y; y[2] += p0.z; y[3] += p0.w;
            y[4] += p1.x; y[5] += p1.y; y[6] += p1.z; y[7] += p1.w;
        }

        float s1 = 0.f, s2 = 0.f;
        #pragma unroll
        for (int j = 0; j < 8; ++j) { s1 += y[j]; s2 += y[j] * y[j]; }
        #pragma unroll
        for (int o = 16; o; o >>= 1) {
            s1 += __shfl_xor_sync(0xffffffffu, s1, o);
            s2 += __shfl_xor_sync(0xffffffffu, s2, o);
        }
        if ((tid & 31) == 0) { red[row_sel][0][wr] = s1; red[row_sel][1][wr] = s2; }
        __syncthreads();
        float t1 = 0.f, t2 = 0.f;
        #pragma unroll
        for (int j = 0; j < 4; ++j) {
            t1 += red[row_sel][0][j];
            t2 += red[row_sel][1][j];
        }
        __syncthreads();

        const float mean = t1 * (1.f / DIM);
        const float var  = t2 * (1.f / DIM) - mean * mean;
        const float rstd = rsqrtf(var + 1e-5f);

        float sv[8];
        #pragma unroll
        for (int j = 0; j < 8; ++j)
            sv[j] = (y[j] - mean) * rstd * gm[j] + bt[j];

        if (t < TLEN - 1) {
            float un[8];
            #pragma unroll
            for (int j = 0; j < 8; ++j) { un[j] = sv[j] + ev[j]; ur[j] = un[j]; }
            split_store8(&g_Uhi[b][d0], &g_Ulo[b][d0], un);
        } else {
            *(float4*)&zout[(size_t)b * DIM + d0] =
                make_float4(sv[0], sv[1], sv[2], sv[3]);
            *(float4*)&zout[(size_t)b * DIM + d0 + 4] =
                make_float4(sv[4], sv[5], sv[6], sv[7]);
        }
        grid_barrier();
    }
}

// ---------------------------------------------------------------------------
// Packed f32x2 helpers (logits kernel)
// ---------------------------------------------------------------------------
__device__ __forceinline__ unsigned long long pack2(float lo, float hi)
{
    unsigned long long r;
    asm("mov.b64 %0, {%1, %2};" : "=l"(r) : "f"(lo), "f"(hi));
    return r;
}
__device__ __forceinline__ float2 unpack2(unsigned long long v)
{
    float2 r;
    asm("mov.b64 {%0, %1}, %2;" : "=f"(r.x), "=f"(r.y) : "l"(v));
    return r;
}
__device__ __forceinline__ void ffma2(unsigned long long& acc,
                                      unsigned long long a, unsigned long long b)
{
    asm("fma.rn.f32x2 %0, %1, %2, %0;" : "+l"(acc) : "l"(a), "l"(b));
}

// ---------------------------------------------------------------------------
// Logits: L[b][v] = sum_d z[b][d] * Wv[d][v] + bv[v]
// ---------------------------------------------------------------------------
__global__ __launch_bounds__(256, 2) void logits_kernel(
    const float* __restrict__ z, const float* __restrict__ Wv,
    const float* __restrict__ bv, float* __restrict__ L)
{
    __shared__ float sS[BT][64];
    __shared__ float sWv[64][VT];

    const int tid = threadIdx.x;
    const int v0  = blockIdx.x * VT;
    const int b0  = blockIdx.y * BT;
    const int vb  = tid & 31;
    const int bg  = tid >> 5;

    unsigned long long acc[4][2];
    #pragma unroll
    for (int i = 0; i < 4; ++i) { acc[i][0] = 0ull; acc[i][1] = 0ull; }

    for (int slab = 0; slab < DIM / 64; ++slab) {
        const int d0 = slab * 64;
        __syncthreads();
        for (int idx = tid; idx < BT * 64; idx += 256)
            sS[idx >> 6][idx & 63] = z[(size_t)(b0 + (idx >> 6)) * DIM + d0 + (idx & 63)];
        for (int idx = tid; idx < 64 * VT; idx += 256)
            sWv[idx >> 7][idx & 127] = Wv[(size_t)(d0 + (idx >> 7)) * VOCAB + v0 + (idx & 127)];
        __syncthreads();

        #pragma unroll 4
        for (int d = 0; d < 64; ++d) {
            const ulonglong2 w2 = *(const ulonglong2*)&sWv[d][vb * 4];
            #pragma unroll
            for (int i = 0; i < 4; ++i) {
                const float u = sS[bg * 4 + i][d];
                const unsigned long long uu = pack2(u, u);
                ffma2(acc[i][0], uu, w2.x);
                ffma2(acc[i][1], uu, w2.y);
            }
        }
    }

    const float4 bvv = *(const float4*)&bv[v0 + vb * 4];
    #pragma unroll
    for (int i = 0; i < 4; ++i) {
        const float2 p0 = unpack2(acc[i][0]);
        const float2 p1 = unpack2(acc[i][1]);
        float4 r = make_float4(p0.x + bvv.x, p0.y + bvv.y,
                               p1.x + bvv.z, p1.y + bvv.w);
        *(float4*)&L[(size_t)(b0 + bg * 4 + i) * VOCAB + v0 + vb * 4] = r;
    }
}

// ---------------------------------------------------------------------------
// In-place log_softmax over each row of L [BATCH][VOCAB]
// ---------------------------------------------------------------------------
__global__ __launch_bounds__(256) void logsoftmax_kernel(float* __restrict__ L)
{
    const int b   = blockIdx.x;
    const int tid = threadIdx.x;
    float* row = L + (size_t)b * VOCAB;
    __shared__ float red[8];

    float m = -1e30f;
    for (int i = tid * 4; i < VOCAB; i += 1024) {
        const float4 v = *(const float4*)&row[i];
        m = fmaxf(m, fmaxf(fmaxf(v.x, v.y), fmaxf(v.z, v.w)));
    }
    #pragma unroll
    for (int o = 16; o; o >>= 1) m = fmaxf(m, __shfl_xor_sync(0xffffffffu, m, o));
    if ((tid & 31) == 0) red[tid >> 5] = m;
    __syncthreads();
    float M = red[0];
    #pragma unroll
    for (int j = 1; j < 8; ++j) M = fmaxf(M, red[j]);
    __syncthreads();

    float s = 0.f;
    for (int i = tid * 4; i < VOCAB; i += 1024) {
        const float4 v = *(const float4*)&row[i];
        s += expf(v.x - M) + expf(v.y - M) + expf(v.z - M) + expf(v.w - M);
    }
    #pragma unroll
    for (int o = 16; o; o >>= 1) s += __shfl_xor_sync(0xffffffffu, s, o);
    if ((tid & 31) == 0) red[tid >> 5] = s;
    __syncthreads();
    float S = 0.f;
    #pragma unroll
    for (int j = 0; j < 8; ++j) S += red[j];
    const float lse = M + logf(S);

    for (int i = tid * 4; i < VOCAB; i += 1024) {
        float4 v = *(const float4*)&row[i];
        v.x -= lse; v.y -= lse; v.z -= lse; v.w -= lse;
        *(float4*)&row[i] = v;
    }
}

// ---------------------------------------------------------------------------
// kernel_launch — 3 graph nodes
// Inputs: 0 hidden [B,1,D] | 1 tokens [B,T] int | 2 emb_out [V,D] | 3 W_dt [2D,D]
//         4 b_dt [D] | 5 gamma [D] | 6 beta [D] | 7 W_v [D,V] | 8 b_v [V]
// Output: [ z (B*D) | y (B*V) ] f32
// ---------------------------------------------------------------------------
extern "C" void kernel_launch(void* const* d_in, const int* in_sizes, int n_in,
                              void* d_out, int out_size)
{
    const float* hidden = (const float*)d_in[0];
    const int*   tok    = (const int*)  d_in[1];
    const float* emb    = (const float*)d_in[2];
    const float* Wdt    = (const float*)d_in[3];
    const float* bdt    = (const float*)d_in[4];
    const float* gamma  = (const float*)d_in[5];
    const float* beta   = (const float*)d_in[6];
    const float* Wv     = (const float*)d_in[7];
    const float* bv     = (const float*)d_in[8];

    float* zout = (float*)d_out;
    float* yout = zout + (size_t)BATCH * DIM;

    cudaFuncSetAttribute(rnn_persistent,
                         cudaFuncAttributeMaxDynamicSharedMemorySize, SMEM_BYTES);

    rnn_persistent<<<NCTA, 256, SMEM_BYTES>>>(hidden, tok, emb, Wdt, bdt, gamma, beta, zout);
    logits_kernel<<<dim3(VOCAB / VT, BATCH / BT), 256>>>(zout, Wv, bv, yout);
    logsoftmax_kernel<<<BATCH, 256>>>(yout);
}